// round 15
// baseline (speedup 1.0000x reference)
#include <cuda_runtime.h>
#include <cstdint>

#define B_ 8
#define C_ 64
#define H_ 256
#define W_ 256
#define HW_ (H_ * W_)
#define TH 4                  // output rows per block
#define ROWS 6                // staged rows (with halo)
#define NS 4                  // ring buffers
#define ROWB (W_ * 4)         // 1024 bytes per smem row (dense)
#define BUFB (ROWS * ROWB)    // 6144 bytes per buffer
#define FULLMASK 0xffffffffu

__device__ __forceinline__ uint32_t smem_u32(const void* p) {
    return (uint32_t)__cvta_generic_to_shared(p);
}
__device__ __forceinline__ void mbar_init(uint32_t mb, uint32_t cnt) {
    asm volatile("mbarrier.init.shared.b64 [%0], %1;" :: "r"(mb), "r"(cnt) : "memory");
}
__device__ __forceinline__ void mbar_expect_tx(uint32_t mb, uint32_t bytes) {
    asm volatile("mbarrier.arrive.expect_tx.shared.b64 _, [%0], %1;"
                 :: "r"(mb), "r"(bytes) : "memory");
}
__device__ __forceinline__ void mbar_arrive(uint32_t mb) {
    asm volatile("mbarrier.arrive.shared.b64 _, [%0];" :: "r"(mb) : "memory");
}
__device__ __forceinline__ void bulk_g2s(uint32_t dst, const void* src, uint32_t bytes, uint32_t mb) {
    asm volatile("cp.async.bulk.shared::cta.global.mbarrier::complete_tx::bytes [%0], [%1], %2, [%3];"
                 :: "r"(dst), "l"(src), "r"(bytes), "r"(mb) : "memory");
}
__device__ __forceinline__ void mbar_wait(uint32_t mb, uint32_t parity) {
    uint32_t done;
    asm volatile("{\n\t.reg .pred p;\n\t"
                 "mbarrier.try_wait.parity.acquire.cta.shared::cta.b64 p, [%1], %2;\n\t"
                 "selp.b32 %0, 1, 0, p;\n\t}"
                 : "=r"(done) : "r"(mb), "r"(parity) : "memory");
    if (!done) {
        asm volatile("{\n\t.reg .pred P1;\n\t"
                     "WL%=:\n\t"
                     "mbarrier.try_wait.parity.acquire.cta.shared::cta.b64 P1, [%0], %1, 0x989680;\n\t"
                     "@P1 bra.uni WD%=;\n\t"
                     "bra.uni WL%=;\n\t"
                     "WD%=:\n\t}"
                     :: "r"(mb), "r"(parity) : "memory");
    }
}

__global__ __launch_bounds__(256, 4)
void conv_attn_v15(const float* __restrict__ q, const float* __restrict__ k,
                   const float* __restrict__ v, float* __restrict__ out)
{
    __shared__ __align__(16) float ring[NS][ROWS][W_];
    __shared__ uint64_t mb_full[NS];
    __shared__ uint64_t mb_empty[NS];

    const int tid  = threadIdx.x;
    const int lane = tid & 31;
    const int x    = tid & 63;          // 64 groups of 4 px; warp = 128 contiguous px of one row
    const int y    = tid >> 6;          // output row 0..3
    const int w0   = x * 4;
    const int h0   = blockIdx.x * TH;
    const int b    = blockIdx.y;

    const size_t cb = (size_t)b * C_ * HW_;
    const float* qb = q + cb;
    const float* kb = k + cb;
    const float* vb = v + cb;
    float*       ob = out + cb;
    const int rowoff = (h0 + y) * W_ + w0;

    // row validity (block-uniform): staged rows r=0..5 map to hh = h0-1+r
    const bool rv0 = (h0 > 0);
    const bool rv5 = (h0 + 4 < H_);
    const uint32_t txbytes = (uint32_t)(4 + (rv0 ? 1 : 0) + (rv5 ? 1 : 0)) * ROWB;

    // zero never-staged border rows once
    if (!rv0) for (int n = 0; n < NS; n++) ring[n][0][tid] = 0.0f;
    if (!rv5) for (int n = 0; n < NS; n++) ring[n][5][tid] = 0.0f;

    const uint32_t ring_s = smem_u32(&ring[0][0][0]);
    const uint32_t mf0 = smem_u32(&mb_full[0]);
    const uint32_t me0 = smem_u32(&mb_empty[0]);
    if (tid < NS) {
        mbar_init(mf0 + tid * 8, 1);    // full: one TMA producer (tx-based)
        mbar_init(me0 + tid * 8, 8);    // empty: one arrival per warp
    }
    __syncthreads();                    // only block-wide barrier in the kernel

    // producer body (tid 0): stage channel-plane at `chan` into buffer bi
    auto stage = [&](const float* chan, int bi) {
        const uint32_t mb = mf0 + bi * 8;
        mbar_expect_tx(mb, txbytes);
        const uint32_t dstb = ring_s + (uint32_t)bi * BUFB;
        #pragma unroll
        for (int r = 0; r < ROWS; r++) {
            if (r == 0 && !rv0) continue;
            if (r == 5 && !rv5) continue;
            bulk_g2s(dstb + (uint32_t)r * ROWB, chan + (r - 1) * W_, ROWB, mb);
        }
    };

    const bool el = (w0 > 0);
    const bool er = (w0 + 4 < W_);

    const char* rb0 = (const char*)ring + (uint32_t)(y * ROWB + w0 * 4);
    const char* rb1 = rb0 + ROWB;
    const char* rb2 = rb1 + ROWB;

    float s[4][9];
#pragma unroll
    for (int j = 0; j < 4; j++)
#pragma unroll
        for (int i = 0; i < 9; i++) s[j][i] = 0.0f;

    uint32_t fp = 0;   // consumer full-parity bits per buffer
    uint32_t ep = 0;   // producer empty-parity bits per buffer (tid0 only)

    // ================= Pass 1: scores =================
    if (tid == 0) {
        stage(kb + (size_t)h0 * W_, 0);
        stage(kb + HW_ + (size_t)h0 * W_, 1);
        stage(kb + 2 * (size_t)HW_ + (size_t)h0 * W_, 2);
    }

    const float* qp = qb + rowoff;
    float4 qcur = *reinterpret_cast<const float4*>(qp);
    const float* kstage = kb + 3 * (size_t)HW_ + (size_t)h0 * W_;

    int bo = 0;
#pragma unroll 1
    for (int c = 0; c < C_; c++) {
        const int bi = c & 3;
        mbar_wait(mf0 + bi * 8, (fp >> bi) & 1);
        fp ^= 1u << bi;

        const float4 qnext = *reinterpret_cast<const float4*>(qp + ((c + 1 < C_) ? HW_ : 0));
        qp += HW_;

        const float qa[4] = {qcur.x, qcur.y, qcur.z, qcur.w};
#pragma unroll
        for (int dy = 0; dy < 3; dy++) {
            const float* rp = (const float*)((dy == 0 ? rb0 : dy == 1 ? rb1 : rb2) + bo);
            const float4 m = *reinterpret_cast<const float4*>(rp);
            float lft = __shfl_up_sync(FULLMASK, m.w, 1);
            float rgt = __shfl_down_sync(FULLMASK, m.x, 1);
            if (lane == 0)  lft = el ? rp[-1] : 0.0f;
            if (lane == 31) rgt = er ? rp[4]  : 0.0f;

            const float a[6] = {lft, m.x, m.y, m.z, m.w, rgt};
#pragma unroll
            for (int j = 0; j < 4; j++)
#pragma unroll
                for (int dx = 0; dx < 3; dx++)
                    s[j][dy * 3 + dx] = fmaf(qa[j], a[j + dx], s[j][dy * 3 + dx]);
        }

        if (lane == 0) mbar_arrive(me0 + bi * 8);   // this warp done with buffer bi

        if (tid == 0 && c + 3 < C_) {
            const int wbi = (c + 3) & 3;
            if (c >= 1) {                            // first staging of each buffer needs no wait
                mbar_wait(me0 + wbi * 8, (ep >> wbi) & 1);
                ep ^= 1u << wbi;
            }
            stage(kstage, wbi);
        }
        kstage += HW_;
        qcur = qnext;
        bo += BUFB; if (bo == NS * BUFB) bo = 0;
    }

    // ================= Softmax over 9 taps (OOB taps = score 0, zero-pad semantics) =================
#pragma unroll
    for (int j = 0; j < 4; j++) {
        float mx = s[j][0];
#pragma unroll
        for (int i = 1; i < 9; i++) mx = fmaxf(mx, s[j][i]);
        float sum = 0.0f;
#pragma unroll
        for (int i = 0; i < 9; i++) { s[j][i] = __expf(s[j][i] - mx); sum += s[j][i]; }
        const float inv = 1.0f / sum;
#pragma unroll
        for (int i = 0; i < 9; i++) s[j][i] *= inv;
    }

    // ================= Pass 2: weighted v sum =================
    // empty barriers carry the WAR edge from pass-1's last consumers; parities continue.
    if (tid == 0) {
#pragma unroll
        for (int c = 0; c < 3; c++) {
            mbar_wait(me0 + c * 8, (ep >> c) & 1);
            ep ^= 1u << c;
            stage(vb + (size_t)c * HW_ + (size_t)h0 * W_, c);
        }
    }

    const float* vstage = vb + 3 * (size_t)HW_ + (size_t)h0 * W_;
    float* op = ob + rowoff;

    bo = 0;
#pragma unroll 1
    for (int c = 0; c < C_; c++) {
        const int bi = c & 3;
        mbar_wait(mf0 + bi * 8, (fp >> bi) & 1);
        fp ^= 1u << bi;

        float acc[4] = {0.f, 0.f, 0.f, 0.f};
#pragma unroll
        for (int dy = 0; dy < 3; dy++) {
            const float* rp = (const float*)((dy == 0 ? rb0 : dy == 1 ? rb1 : rb2) + bo);
            const float4 m = *reinterpret_cast<const float4*>(rp);
            float lft = __shfl_up_sync(FULLMASK, m.w, 1);
            float rgt = __shfl_down_sync(FULLMASK, m.x, 1);
            if (lane == 0)  lft = el ? rp[-1] : 0.0f;
            if (lane == 31) rgt = er ? rp[4]  : 0.0f;

            const float a[6] = {lft, m.x, m.y, m.z, m.w, rgt};
#pragma unroll
            for (int j = 0; j < 4; j++)
#pragma unroll
                for (int dx = 0; dx < 3; dx++)
                    acc[j] = fmaf(s[j][dy * 3 + dx], a[j + dx], acc[j]);
        }

        if (lane == 0) mbar_arrive(me0 + bi * 8);

        if (tid == 0 && c + 3 < C_) {
            const int wbi = (c + 3) & 3;
            mbar_wait(me0 + wbi * 8, (ep >> wbi) & 1);
            ep ^= 1u << wbi;
            stage(vstage, wbi);
        }
        vstage += HW_;

        float4 o;
        o.x = acc[0]; o.y = acc[1]; o.z = acc[2]; o.w = acc[3];
        *reinterpret_cast<float4*>(op) = o;
        op += HW_;
        bo += BUFB; if (bo == NS * BUFB) bo = 0;
    }
}

extern "C" void kernel_launch(void* const* d_in, const int* in_sizes, int n_in,
                              void* d_out, int out_size)
{
    const float* q = (const float*)d_in[0];
    const float* k = (const float*)d_in[1];
    const float* v = (const float*)d_in[2];
    float* out = (float*)d_out;

    dim3 block(256);
    dim3 grid(H_ / TH, B_);     // 64 x 8 = 512 blocks
    conv_attn_v15<<<grid, block>>>(q, k, v, out);
}